// round 13
// baseline (speedup 1.0000x reference)
#include <cuda_runtime.h>
#include <cuda_bf16.h>
#include <math.h>
#include <stdint.h>

#define B_     1024
#define VOCAB  32000
#define D_     128
#define KNEG   5
#define ROWS_T 7168          // 1024 vi + 1024 vo + 5120 neg
#define RTILES 56            // 128-row tiles
#define SPLITS 5
#define CHUNK  6400          // VOCAB / SPLITS
#define ITERS  200           // CHUNK / 32

// smem:  A: [m=128][k=32] bf16, row pitch 80B.  B: [k=32][d=128] bf16,
// row 256B, 16B-chunk XOR-swizzled by (k&7).  Double buffered.
// 128 threads (4 warps of 64x64), 2 CTAs/SM.
#define A_ROWB  80
#define A_BUF   (128 * A_ROWB)    // 10240
#define B_BUF   (32 * 256)        // 8192
#define SMEMSZ  (2 * A_BUF + 2 * B_BUF)   // 36864

// ---------------- device scratch ----------------
__device__ float g_part[SPLITS][ROWS_T][D_];   // split-K partials (18.3 MB)
__device__ float g_s[B_];
__device__ float g_bm[B_ * KNEG];

// ---------------- helpers ----------------
__device__ __forceinline__ uint32_t smem_u32(const void* p) {
    uint32_t a;
    asm("{ .reg .u64 t; cvta.to.shared.u64 t, %1; cvt.u32.u64 %0, t; }" : "=r"(a) : "l"(p));
    return a;
}
__device__ __forceinline__ uint32_t pack_bf16(float lo, float hi) {
    uint32_t u;
    asm("cvt.rn.bf16x2.f32 %0, %1, %2;" : "=r"(u) : "f"(hi), "f"(lo));
    return u;
}
__device__ __forceinline__ void ldsm4(uint32_t r[4], uint32_t addr) {
    asm volatile("ldmatrix.sync.aligned.m8n8.x4.shared.b16 {%0,%1,%2,%3}, [%4];"
                 : "=r"(r[0]), "=r"(r[1]), "=r"(r[2]), "=r"(r[3]) : "r"(addr));
}
__device__ __forceinline__ void ldsm4t(uint32_t r[4], uint32_t addr) {
    asm volatile("ldmatrix.sync.aligned.m8n8.x4.trans.shared.b16 {%0,%1,%2,%3}, [%4];"
                 : "=r"(r[0]), "=r"(r[1]), "=r"(r[2]), "=r"(r[3]) : "r"(addr));
}
__device__ __forceinline__ void mma16(float c[4], const uint32_t a[4], const uint32_t b[2]) {
    asm volatile(
        "mma.sync.aligned.m16n8k16.row.col.f32.bf16.bf16.f32 "
        "{%0,%1,%2,%3}, {%4,%5,%6,%7}, {%8,%9}, {%0,%1,%2,%3};"
        : "+f"(c[0]), "+f"(c[1]), "+f"(c[2]), "+f"(c[3])
        : "r"(a[0]), "r"(a[1]), "r"(a[2]), "r"(a[3]), "r"(b[0]), "r"(b[1]));
}

// ---------------- kernel 1: C_part[sp] = X_tile @ Y_chunk ----------------
// CTA tile 128m x 128n, BK=32.  4 warps as 2(m) x 2(n), warp tile 64x64.
// 2 CTAs/SM; single __syncthreads per iter.
// A staged one iter ahead (DRAM); B loaded+staged within the iter (L2-resident).
__global__ __launch_bounds__(128, 2) void gemm_all(const float* __restrict__ vi,
                                                   const float* __restrict__ vo,
                                                   const float* __restrict__ neg,
                                                   const float* __restrict__ V,
                                                   const float* __restrict__ U) {
    __shared__ __align__(16) char smem[SMEMSZ];

    const int mt = blockIdx.x;                // row-tile 0..55
    const int sp = blockIdx.y;                // split   0..4
    const int row0 = mt * 128;
    const float* X = (mt < 8)  ? vi  + (size_t)row0 * VOCAB
                   : (mt < 16) ? vo  + (size_t)(row0 - 1024) * VOCAB
                               : neg + (size_t)(row0 - 2048) * VOCAB;
    const float* Y = (mt < 8) ? V : U;
    const int kk0 = sp * CHUNK;

    const int tid = threadIdx.x, lane = tid & 31, wid = tid >> 5;
    const int wm = wid >> 1, wn = wid & 1;    // 2 x 2

    const uint32_t sb = smem_u32(smem);

    // ---- loader roles (coalesced) ----
    // A: pass s (0..7): row = s*16 + (tid>>3), float4 col = tid&7
    const int ar = tid >> 3;
    const int ac = tid & 7;
    // B: pass s (0..7): row = s*4 + (tid>>5), float4 col = lane
    const int br = tid >> 5;
    const int bc = lane;

    // ---- fragment addresses (validated maps; warp m-span 64) ----
    const uint32_t a_off = (uint32_t)(wm * 64 + (lane & 15)) * A_ROWB + ((lane >> 4) << 4);
    const int kl = (lane & 7) + ((lane >> 3) & 1) * 8;
    uint32_t b_swz[4];
    #pragma unroll
    for (int jj = 0; jj < 4; jj++)
        b_swz[jj] = (uint32_t)(((wn * 8 + jj * 2 + (lane >> 4)) ^ (lane & 7)) << 4);
    const uint32_t b_off = (uint32_t)kl * 256;

    float c[4][8][4] = {};
    float4 xa[8];                             // A staging: live across one iter

    auto ldg_a = [&](int it) {
        const int kk = kk0 + it * 32;
        #pragma unroll
        for (int s = 0; s < 8; s++)
            xa[s] = *(const float4*)(X + (size_t)(s * 16 + ar) * VOCAB + kk + ac * 4);
    };
    auto sts_a = [&](uint32_t buf) {
        char* abase = smem + buf * A_BUF;
        #pragma unroll
        for (int s = 0; s < 8; s++) {
            uint2 v = make_uint2(pack_bf16(xa[s].x, xa[s].y),
                                 pack_bf16(xa[s].z, xa[s].w));
            *(uint2*)(abase + (s * 16 + ar) * A_ROWB + ac * 8) = v;
        }
    };
    // B: load + store within the iteration (L2-resident; short live range)
    auto load_b = [&](int it, uint32_t buf) {
        const int kk = kk0 + it * 32;
        float4 yb[8];
        #pragma unroll
        for (int s = 0; s < 8; s++)
            yb[s] = *(const float4*)(Y + (size_t)(kk + s * 4 + br) * D_ + bc * 4);
        char* bbase = smem + 2 * A_BUF + buf * B_BUF;
        #pragma unroll
        for (int s = 0; s < 8; s++) {
            int row = s * 4 + br;
            int chs = (bc >> 1) ^ (row & 7);
            uint2 v = make_uint2(pack_bf16(yb[s].x, yb[s].y),
                                 pack_bf16(yb[s].z, yb[s].w));
            *(uint2*)(bbase + row * 256 + chs * 16 + (bc & 1) * 8) = v;
        }
    };

    // ---- prologue: buf0 <- iter0; xa <- iter1 ----
    ldg_a(0);
    sts_a(0);
    load_b(0, 0);
    ldg_a(1);
    __syncthreads();

    for (int it = 0; it < ITERS; it++) {
        const uint32_t cur = (uint32_t)(it & 1);
        const uint32_t abuf = sb + cur * A_BUF;
        const uint32_t bbuf = sb + 2 * A_BUF + cur * B_BUF;

        // stage it+1: A from regs (loaded last iter), B load+store now (L2 hit)
        if (it + 1 < ITERS) {
            sts_a(cur ^ 1);
            load_b(it + 1, cur ^ 1);
        }
        // prefetch A for it+2 (DRAM latency covered by this iter's MMA)
        if (it + 2 < ITERS)
            ldg_a(it + 2);

        // ---- MMA on current buffer ----
        #pragma unroll
        for (int ks = 0; ks < 2; ks++) {
            uint32_t af[4][4];
            #pragma unroll
            for (int i = 0; i < 4; i++)
                ldsm4(af[i], abuf + a_off + i * (16 * A_ROWB) + ks * 32);
            const uint32_t brow_b = bbuf + b_off + ks * 16 * 256;
            #pragma unroll
            for (int jj = 0; jj < 4; jj++) {
                uint32_t bf[4];
                ldsm4t(bf, brow_b + b_swz[jj]);
                #pragma unroll
                for (int i = 0; i < 4; i++) {
                    mma16(c[i][jj * 2],     af[i], bf);
                    mma16(c[i][jj * 2 + 1], af[i], bf + 2);
                }
            }
        }

        __syncthreads();
    }

    // ---- epilogue: disjoint partial writes ----
    const int g = lane >> 2, t = lane & 3;
    float* P = &g_part[sp][row0][0];
    #pragma unroll
    for (int i = 0; i < 4; i++) {
        #pragma unroll
        for (int j = 0; j < 8; j++) {
            int m = wm * 64 + i * 16;
            int col = wn * 64 + j * 8 + 2 * t;
            *(float2*)&P[(size_t)(m + g) * D_ + col]     = make_float2(c[i][j][0], c[i][j][1]);
            *(float2*)&P[(size_t)(m + g + 8) * D_ + col] = make_float2(c[i][j][2], c[i][j][3]);
        }
    }
}

// ---------------- kernel 2: reduce partials + per-b dot products ----------------
__global__ __launch_bounds__(256) void finalize_a() {
    const int wid = threadIdx.x >> 5, lane = threadIdx.x & 31;
    const int b = blockIdx.x * 8 + wid;
    const int d = lane * 4;

    float4 e = make_float4(0.f, 0.f, 0.f, 0.f);
    float4 p = make_float4(0.f, 0.f, 0.f, 0.f);
    float4 nk[KNEG];
    #pragma unroll
    for (int k = 0; k < KNEG; k++) nk[k] = make_float4(0.f, 0.f, 0.f, 0.f);

    #pragma unroll
    for (int sp = 0; sp < SPLITS; sp++) {
        float4 v;
        v = *(const float4*)&g_part[sp][b][d];
        e.x += v.x; e.y += v.y; e.z += v.z; e.w += v.w;
        v = *(const float4*)&g_part[sp][1024 + b][d];
        p.x += v.x; p.y += v.y; p.z += v.z; p.w += v.w;
        #pragma unroll
        for (int k = 0; k < KNEG; k++) {
            v = *(const float4*)&g_part[sp][2048 + b * KNEG + k][d];
            nk[k].x += v.x; nk[k].y += v.y; nk[k].z += v.z; nk[k].w += v.w;
        }
    }

    float s = e.x * p.x + e.y * p.y + e.z * p.z + e.w * p.w;
    float bm[KNEG];
    #pragma unroll
    for (int k = 0; k < KNEG; k++)
        bm[k] = e.x * nk[k].x + e.y * nk[k].y + e.z * nk[k].z + e.w * nk[k].w;

    #pragma unroll
    for (int off = 16; off; off >>= 1) {
        s += __shfl_xor_sync(0xffffffffu, s, off);
        #pragma unroll
        for (int k = 0; k < KNEG; k++)
            bm[k] += __shfl_xor_sync(0xffffffffu, bm[k], off);
    }
    if (lane == 0) {
        g_s[b] = s;
        #pragma unroll
        for (int k = 0; k < KNEG; k++) g_bm[b * KNEG + k] = bm[k];
    }
}

// ---------------- kernel 3: loss ----------------
__device__ __forceinline__ float logsig(float x) {
    return fminf(x, 0.f) - log1pf(expf(-fabsf(x)));
}

__global__ void finalize_kernel(float* __restrict__ out) {
    __shared__ float red[B_];
    int b = threadIdx.x;
    float left  = logsig(g_s[b]);
    float right = 0.f;
    #pragma unroll
    for (int k = 0; k < KNEG; k++)
        right += logsig(-g_bm[b * KNEG + k]);
    red[b] = -(left + right);
    __syncthreads();
    for (int off = B_ / 2; off > 0; off >>= 1) {
        if (b < off) red[b] += red[b + off];
        __syncthreads();
    }
    if (b == 0) out[0] = red[0] / (float)B_;
}

// ---------------- launch ----------------
extern "C" void kernel_launch(void* const* d_in, const int* in_sizes, int n_in,
                              void* d_out, int out_size) {
    const float* vi  = (const float*)d_in[0];   // [B, VOC]
    const float* vo  = (const float*)d_in[1];   // [B, VOC]
    const float* neg = (const float*)d_in[2];   // [B, K, VOC]
    const float* V   = (const float*)d_in[3];   // [VOC, D]
    const float* U   = (const float*)d_in[4];   // [VOC, D]
    float* out = (float*)d_out;

    gemm_all<<<dim3(RTILES, SPLITS), 128>>>(vi, vo, neg, V, U);
    finalize_a<<<B_ / 8, 256>>>();
    finalize_kernel<<<1, B_>>>(out);
}

// round 14
// speedup vs baseline: 1.1478x; 1.1478x over previous
#include <cuda_runtime.h>
#include <cuda_bf16.h>
#include <math.h>
#include <stdint.h>

#define B_     1024
#define VOCAB  32000
#define D_     128
#define KNEG   5
#define ROWS_T 7168          // 1024 vi + 1024 vo + 5120 neg
#define RTILES 28            // 256-row tiles
#define SPLITS 5
#define CHUNK  6400          // VOCAB / SPLITS
#define ITERS  100           // CHUNK / 64   (BK = 64)

// smem:  A: [m=256][k=64] bf16, row 128B data + 16B pad = 144B pitch.
//        B: [k=64][d=128] bf16, row 256B, 16B-chunk XOR-swizzled by (k&7).
// Double buffered (dynamic smem, 1 CTA/SM).
#define A_ROWB  144
#define A_BUF   (256 * A_ROWB)    // 36864
#define B_BUF   (64 * 256)        // 16384
#define SMEM_DYN (2 * A_BUF + 2 * B_BUF)   // 106496

// ---------------- device scratch ----------------
__device__ float g_part[SPLITS][ROWS_T][D_];   // split-K partials (18.3 MB)
__device__ float g_s[B_];
__device__ float g_bm[B_ * KNEG];

// ---------------- helpers ----------------
__device__ __forceinline__ uint32_t smem_u32(const void* p) {
    uint32_t a;
    asm("{ .reg .u64 t; cvta.to.shared.u64 t, %1; cvt.u32.u64 %0, t; }" : "=r"(a) : "l"(p));
    return a;
}
__device__ __forceinline__ uint32_t pack_bf16(float lo, float hi) {
    uint32_t u;
    asm("cvt.rn.bf16x2.f32 %0, %1, %2;" : "=r"(u) : "f"(hi), "f"(lo));
    return u;
}
__device__ __forceinline__ void ldsm4(uint32_t r[4], uint32_t addr) {
    asm volatile("ldmatrix.sync.aligned.m8n8.x4.shared.b16 {%0,%1,%2,%3}, [%4];"
                 : "=r"(r[0]), "=r"(r[1]), "=r"(r[2]), "=r"(r[3]) : "r"(addr));
}
__device__ __forceinline__ void ldsm4t(uint32_t r[4], uint32_t addr) {
    asm volatile("ldmatrix.sync.aligned.m8n8.x4.trans.shared.b16 {%0,%1,%2,%3}, [%4];"
                 : "=r"(r[0]), "=r"(r[1]), "=r"(r[2]), "=r"(r[3]) : "r"(addr));
}
__device__ __forceinline__ void mma16(float c[4], const uint32_t a[4], const uint32_t b[2]) {
    asm volatile(
        "mma.sync.aligned.m16n8k16.row.col.f32.bf16.bf16.f32 "
        "{%0,%1,%2,%3}, {%4,%5,%6,%7}, {%8,%9}, {%0,%1,%2,%3};"
        : "+f"(c[0]), "+f"(c[1]), "+f"(c[2]), "+f"(c[3])
        : "r"(a[0]), "r"(a[1]), "r"(a[2]), "r"(a[3]), "r"(b[0]), "r"(b[1]));
}

// ---------------- kernel 1: C_part[sp] = X_tile @ Y_chunk ----------------
// CTA tile 256m x 128n, BK=64.  8 warps as 4(m) x 2(n), warp tile 64x64.
// Staging in two 32-k halves reusing the same registers; ONE barrier / 64-k iter.
__global__ __launch_bounds__(256, 1) void gemm_all(const float* __restrict__ vi,
                                                   const float* __restrict__ vo,
                                                   const float* __restrict__ neg,
                                                   const float* __restrict__ V,
                                                   const float* __restrict__ U) {
    extern __shared__ __align__(16) char smem[];

    const int mt = blockIdx.x;                // row-tile 0..27
    const int sp = blockIdx.y;                // split   0..4
    const int row0 = mt * 256;
    const float* X = (mt < 4) ? vi  + (size_t)row0 * VOCAB
                   : (mt < 8) ? vo  + (size_t)(row0 - 1024) * VOCAB
                              : neg + (size_t)(row0 - 2048) * VOCAB;
    const float* Y = (mt < 4) ? V : U;
    const int kk0 = sp * CHUNK;

    const int tid = threadIdx.x, lane = tid & 31, wid = tid >> 5;
    const int wm = wid >> 1, wn = wid & 1;    // 4 x 2

    const uint32_t sb = smem_u32(smem);

    // ---- loader roles (coalesced; validated) ----
    const int ar = tid >> 3;                  // A: row within pass (s*32 + ar)
    const int ac = tid & 7;                   // A: float4 col (within 32-k half)
    const int br = tid >> 5;                  // B: row within pass (s*8 + br)
    const int bc = lane;                      // B: float4 col

    // ---- fragment addresses (validated maps; A pitch now 144B) ----
    const uint32_t a_off = (uint32_t)(wm * 64 + (lane & 15)) * A_ROWB + ((lane >> 4) << 4);
    const int kl = (lane & 7) + ((lane >> 3) & 1) * 8;
    uint32_t b_swz[4];
    #pragma unroll
    for (int jj = 0; jj < 4; jj++)
        b_swz[jj] = (uint32_t)(((wn * 8 + jj * 2 + (lane >> 4)) ^ (lane & 7)) << 4);
    const uint32_t b_off = (uint32_t)kl * 256;

    float c[4][8][4] = {};
    float4 xa[8], yb[4];

    // ---- staging helpers: one 32-k half at a time ----
    auto do_ldg = [&](int it, int h) {
        const int kk = kk0 + it * 64 + h * 32;
        #pragma unroll
        for (int s = 0; s < 8; s++)
            xa[s] = *(const float4*)(X + (size_t)(s * 32 + ar) * VOCAB + kk + ac * 4);
        #pragma unroll
        for (int s = 0; s < 4; s++)
            yb[s] = *(const float4*)(Y + (size_t)(kk + s * 8 + br) * D_ + bc * 4);
    };
    auto do_sts = [&](uint32_t buf, int h) {
        char* abase = smem + buf * A_BUF;
        #pragma unroll
        for (int s = 0; s < 8; s++) {
            uint2 v = make_uint2(pack_bf16(xa[s].x, xa[s].y),
                                 pack_bf16(xa[s].z, xa[s].w));
            *(uint2*)(abase + (s * 32 + ar) * A_ROWB + h * 64 + ac * 8) = v;
        }
        char* bbase = smem + 2 * A_BUF + buf * B_BUF;
        #pragma unroll
        for (int s = 0; s < 4; s++) {
            int row = h * 32 + s * 8 + br;
            int chs = (bc >> 1) ^ (row & 7);
            uint2 v = make_uint2(pack_bf16(yb[s].x, yb[s].y),
                                 pack_bf16(yb[s].z, yb[s].w));
            *(uint2*)(bbase + row * 256 + chs * 16 + (bc & 1) * 8) = v;
        }
    };

    // ---- one k16 MMA step ----
    auto mma_step = [&](uint32_t abuf, uint32_t bbuf, int ks) {
        uint32_t af[4][4];
        #pragma unroll
        for (int i = 0; i < 4; i++)
            ldsm4(af[i], abuf + a_off + i * (16 * A_ROWB) + ks * 32);
        const uint32_t brow_b = bbuf + b_off + (uint32_t)ks * (16 * 256);
        #pragma unroll
        for (int jj = 0; jj < 4; jj++) {
            uint32_t bf[4];
            ldsm4t(bf, brow_b + b_swz[jj]);
            #pragma unroll
            for (int i = 0; i < 4; i++) {
                mma16(c[i][jj * 2],     af[i], bf);
                mma16(c[i][jj * 2 + 1], af[i], bf + 2);
            }
        }
    };

    // ---- prologue: fill buf0 with iter0 ----
    do_ldg(0, 0); do_sts(0, 0);
    do_ldg(0, 1); do_sts(0, 1);
    __syncthreads();

    for (int it = 0; it < ITERS; it++) {
        const uint32_t cur = (uint32_t)(it & 1);
        const uint32_t nxt = cur ^ 1;
        const uint32_t abuf = sb + cur * A_BUF;
        const uint32_t bbuf = sb + 2 * A_BUF + cur * B_BUF;

        // issue half0 LDG early so data lands during the first MMA block
        if (it + 1 < ITERS) do_ldg(it + 1, 0);

        mma_step(abuf, bbuf, 0);
        mma_step(abuf, bbuf, 1);

        if (it + 1 < ITERS) {
            do_sts(nxt, 0);           // half0 regs -> smem
            do_ldg(it + 1, 1);        // issue half1 LDG
        }

        mma_step(abuf, bbuf, 2);
        mma_step(abuf, bbuf, 3);

        if (it + 1 < ITERS)
            do_sts(nxt, 1);           // half1 regs -> smem

        __syncthreads();
    }

    // ---- epilogue: disjoint partial writes ----
    const int g = lane >> 2, t = lane & 3;
    float* P = &g_part[sp][row0][0];
    #pragma unroll
    for (int i = 0; i < 4; i++) {
        #pragma unroll
        for (int j = 0; j < 8; j++) {
            int m = wm * 64 + i * 16;
            int col = wn * 64 + j * 8 + 2 * t;
            *(float2*)&P[(size_t)(m + g) * D_ + col]     = make_float2(c[i][j][0], c[i][j][1]);
            *(float2*)&P[(size_t)(m + g + 8) * D_ + col] = make_float2(c[i][j][2], c[i][j][3]);
        }
    }
}

// ---------------- kernel 2: reduce partials + per-b dot products ----------------
__global__ __launch_bounds__(256) void finalize_a() {
    const int wid = threadIdx.x >> 5, lane = threadIdx.x & 31;
    const int b = blockIdx.x * 8 + wid;
    const int d = lane * 4;

    float4 e = make_float4(0.f, 0.f, 0.f, 0.f);
    float4 p = make_float4(0.f, 0.f, 0.f, 0.f);
    float4 nk[KNEG];
    #pragma unroll
    for (int k = 0; k < KNEG; k++) nk[k] = make_float4(0.f, 0.f, 0.f, 0.f);

    #pragma unroll
    for (int sp = 0; sp < SPLITS; sp++) {
        float4 v;
        v = *(const float4*)&g_part[sp][b][d];
        e.x += v.x; e.y += v.y; e.z += v.z; e.w += v.w;
        v = *(const float4*)&g_part[sp][1024 + b][d];
        p.x += v.x; p.y += v.y; p.z += v.z; p.w += v.w;
        #pragma unroll
        for (int k = 0; k < KNEG; k++) {
            v = *(const float4*)&g_part[sp][2048 + b * KNEG + k][d];
            nk[k].x += v.x; nk[k].y += v.y; nk[k].z += v.z; nk[k].w += v.w;
        }
    }

    float s = e.x * p.x + e.y * p.y + e.z * p.z + e.w * p.w;
    float bm[KNEG];
    #pragma unroll
    for (int k = 0; k < KNEG; k++)
        bm[k] = e.x * nk[k].x + e.y * nk[k].y + e.z * nk[k].z + e.w * nk[k].w;

    #pragma unroll
    for (int off = 16; off; off >>= 1) {
        s += __shfl_xor_sync(0xffffffffu, s, off);
        #pragma unroll
        for (int k = 0; k < KNEG; k++)
            bm[k] += __shfl_xor_sync(0xffffffffu, bm[k], off);
    }
    if (lane == 0) {
        g_s[b] = s;
        #pragma unroll
        for (int k = 0; k < KNEG; k++) g_bm[b * KNEG + k] = bm[k];
    }
}

// ---------------- kernel 3: loss ----------------
__device__ __forceinline__ float logsig(float x) {
    return fminf(x, 0.f) - log1pf(expf(-fabsf(x)));
}

__global__ void finalize_kernel(float* __restrict__ out) {
    __shared__ float red[B_];
    int b = threadIdx.x;
    float left  = logsig(g_s[b]);
    float right = 0.f;
    #pragma unroll
    for (int k = 0; k < KNEG; k++)
        right += logsig(-g_bm[b * KNEG + k]);
    red[b] = -(left + right);
    __syncthreads();
    for (int off = B_ / 2; off > 0; off >>= 1) {
        if (b < off) red[b] += red[b + off];
        __syncthreads();
    }
    if (b == 0) out[0] = red[0] / (float)B_;
}

// ---------------- launch ----------------
extern "C" void kernel_launch(void* const* d_in, const int* in_sizes, int n_in,
                              void* d_out, int out_size) {
    const float* vi  = (const float*)d_in[0];   // [B, VOC]
    const float* vo  = (const float*)d_in[1];   // [B, VOC]
    const float* neg = (const float*)d_in[2];   // [B, K, VOC]
    const float* V   = (const float*)d_in[3];   // [VOC, D]
    const float* U   = (const float*)d_in[4];   // [VOC, D]
    float* out = (float*)d_out;

    cudaFuncSetAttribute(gemm_all, cudaFuncAttributeMaxDynamicSharedMemorySize, SMEM_DYN);

    gemm_all<<<dim3(RTILES, SPLITS), 256, SMEM_DYN>>>(vi, vo, neg, V, U);
    finalize_a<<<B_ / 8, 256>>>();
    finalize_kernel<<<1, B_>>>(out);
}

// round 15
// speedup vs baseline: 1.2156x; 1.0591x over previous
#include <cuda_runtime.h>
#include <cuda_bf16.h>
#include <math.h>
#include <stdint.h>

#define B_     1024
#define VOCAB  32000
#define D_     128
#define KNEG   5
#define ROWS_T 7168          // 1024 vi + 1024 vo + 5120 neg
#define RTILES 28            // 256-row tiles
#define SPLITS 5
#define CHUNK  6400          // VOCAB / SPLITS
#define ITERS  200           // CHUNK / 32

// smem:  A: [m=256][k=32] bf16, row pitch 80B.  B: [k=32][d=128] bf16,
// row 256B, 16B-chunk XOR-swizzled by (k&7).  Double buffered, 1 CTA/SM.
#define A_ROWB  80
#define A_BUF   (256 * A_ROWB)    // 20480
#define B_BUF   (32 * 256)        // 8192
#define SMEMSZ  (2 * A_BUF + 2 * B_BUF)   // 57344

// ---------------- device scratch ----------------
__device__ float g_part[SPLITS][ROWS_T][D_];   // split-K partials (18.3 MB)
__device__ float g_s[B_];
__device__ float g_bm[B_ * KNEG];

// ---------------- helpers ----------------
__device__ __forceinline__ uint32_t smem_u32(const void* p) {
    uint32_t a;
    asm("{ .reg .u64 t; cvta.to.shared.u64 t, %1; cvt.u32.u64 %0, t; }" : "=r"(a) : "l"(p));
    return a;
}
__device__ __forceinline__ uint32_t pack_bf16(float lo, float hi) {
    uint32_t u;
    asm("cvt.rn.bf16x2.f32 %0, %1, %2;" : "=r"(u) : "f"(hi), "f"(lo));
    return u;
}
__device__ __forceinline__ void ldsm4(uint32_t r[4], uint32_t addr) {
    asm volatile("ldmatrix.sync.aligned.m8n8.x4.shared.b16 {%0,%1,%2,%3}, [%4];"
                 : "=r"(r[0]), "=r"(r[1]), "=r"(r[2]), "=r"(r[3]) : "r"(addr));
}
__device__ __forceinline__ void ldsm4t(uint32_t r[4], uint32_t addr) {
    asm volatile("ldmatrix.sync.aligned.m8n8.x4.trans.shared.b16 {%0,%1,%2,%3}, [%4];"
                 : "=r"(r[0]), "=r"(r[1]), "=r"(r[2]), "=r"(r[3]) : "r"(addr));
}
__device__ __forceinline__ void mma16(float c[4], const uint32_t a[4], const uint32_t b[2]) {
    asm volatile(
        "mma.sync.aligned.m16n8k16.row.col.f32.bf16.bf16.f32 "
        "{%0,%1,%2,%3}, {%4,%5,%6,%7}, {%8,%9}, {%0,%1,%2,%3};"
        : "+f"(c[0]), "+f"(c[1]), "+f"(c[2]), "+f"(c[3])
        : "r"(a[0]), "r"(a[1]), "r"(a[2]), "r"(a[3]), "r"(b[0]), "r"(b[1]));
}

// ---------------- kernel 1: C_part[sp] = X_tile @ Y_chunk ----------------
// CTA tile 256m x 128n, BK=32.  8 warps as 4(m) x 2(n), warp tile 64x64.
// Loop body: STS(it+1) -> LDG(it+2) -> MMA(it) -> barrier.
// STS issued at the TOP so they fully drain before the barrier (no drain cost).
__global__ __launch_bounds__(256, 1) void gemm_all(const float* __restrict__ vi,
                                                   const float* __restrict__ vo,
                                                   const float* __restrict__ neg,
                                                   const float* __restrict__ V,
                                                   const float* __restrict__ U) {
    __shared__ __align__(16) char smem[SMEMSZ];

    const int mt = blockIdx.x;                // row-tile 0..27
    const int sp = blockIdx.y;                // split   0..4
    const int row0 = mt * 256;
    const float* X = (mt < 4) ? vi  + (size_t)row0 * VOCAB
                   : (mt < 8) ? vo  + (size_t)(row0 - 1024) * VOCAB
                              : neg + (size_t)(row0 - 2048) * VOCAB;
    const float* Y = (mt < 4) ? V : U;
    const int kk0 = sp * CHUNK;

    const int tid = threadIdx.x, lane = tid & 31, wid = tid >> 5;
    const int wm = wid >> 1, wn = wid & 1;    // 4 x 2

    const uint32_t sb = smem_u32(smem);

    // ---- loader roles (coalesced; validated) ----
    const int ar = tid >> 3;                  // A: row within pass (s*32 + ar)
    const int ac = tid & 7;                   // A: float4 col
    const int br = tid >> 5;                  // B: row within pass (s*8 + br)
    const int bc = lane;                      // B: float4 col

    // ---- fragment addresses (validated maps; warp m-span 64) ----
    const uint32_t a_off = (uint32_t)(wm * 64 + (lane & 15)) * A_ROWB + ((lane >> 4) << 4);
    const int kl = (lane & 7) + ((lane >> 3) & 1) * 8;
    uint32_t b_swz[4];
    #pragma unroll
    for (int jj = 0; jj < 4; jj++)
        b_swz[jj] = (uint32_t)(((wn * 8 + jj * 2 + (lane >> 4)) ^ (lane & 7)) << 4);
    const uint32_t b_off = (uint32_t)kl * 256;

    float c[4][8][4] = {};
    float4 xa[8], yb[4];

    // ---- staging helpers ----
    auto do_ldg = [&](int it) {
        const int kk = kk0 + it * 32;
        #pragma unroll
        for (int s = 0; s < 8; s++)
            xa[s] = *(const float4*)(X + (size_t)(s * 32 + ar) * VOCAB + kk + ac * 4);
        #pragma unroll
        for (int s = 0; s < 4; s++)
            yb[s] = *(const float4*)(Y + (size_t)(kk + s * 8 + br) * D_ + bc * 4);
    };
    auto do_sts = [&](uint32_t aoff_buf, uint32_t boff_buf) {
        char* abase = smem + aoff_buf;
        #pragma unroll
        for (int s = 0; s < 8; s++) {
            uint2 v = make_uint2(pack_bf16(xa[s].x, xa[s].y),
                                 pack_bf16(xa[s].z, xa[s].w));
            *(uint2*)(abase + (s * 32 + ar) * A_ROWB + ac * 8) = v;
        }
        char* bbase = smem + 2 * A_BUF + boff_buf;
        #pragma unroll
        for (int s = 0; s < 4; s++) {
            int row = s * 8 + br;
            int chs = (bc >> 1) ^ (row & 7);
            uint2 v = make_uint2(pack_bf16(yb[s].x, yb[s].y),
                                 pack_bf16(yb[s].z, yb[s].w));
            *(uint2*)(bbase + row * 256 + chs * 16 + (bc & 1) * 8) = v;
        }
    };

    // ---- prologue: buf0 <- iter0, regs <- iter1 ----
    do_ldg(0);
    do_sts(0, 0);
    do_ldg(1);
    __syncthreads();

    for (int it = 0; it < ITERS; it++) {
        const uint32_t cur = (uint32_t)(it & 1);
        const uint32_t abuf = sb + cur * A_BUF;
        const uint32_t bbuf = sb + 2 * A_BUF + cur * B_BUF;

        // ---- 1) stage it+1 into other buffer FIRST (drains during MMA) ----
        if (it + 1 < ITERS)
            do_sts((cur ^ 1) * A_BUF, (cur ^ 1) * B_BUF);
        // ---- 2) prefetch it+2 (regs just freed by the STS) ----
        if (it + 2 < ITERS)
            do_ldg(it + 2);

        // ---- 3) MMA on current buffer ----
        #pragma unroll
        for (int ks = 0; ks < 2; ks++) {
            uint32_t af[4][4];
            #pragma unroll
            for (int i = 0; i < 4; i++)
                ldsm4(af[i], abuf + a_off + i * (16 * A_ROWB) + ks * 32);
            const uint32_t brow_b = bbuf + b_off + ks * 16 * 256;
            #pragma unroll
            for (int jj = 0; jj < 4; jj++) {
                uint32_t bf[4];
                ldsm4t(bf, brow_b + b_swz[jj]);
                #pragma unroll
                for (int i = 0; i < 4; i++) {
                    mma16(c[i][jj * 2],     af[i], bf);
                    mma16(c[i][jj * 2 + 1], af[i], bf + 2);
                }
            }
        }

        // ---- 4) barrier (STS long drained; near-zero drain cost) ----
        __syncthreads();
    }

    // ---- epilogue: disjoint partial writes ----
    const int g = lane >> 2, t = lane & 3;
    float* P = &g_part[sp][row0][0];
    #pragma unroll
    for (int i = 0; i < 4; i++) {
        #pragma unroll
        for (int j = 0; j < 8; j++) {
            int m = wm * 64 + i * 16;
            int col = wn * 64 + j * 8 + 2 * t;
            *(float2*)&P[(size_t)(m + g) * D_ + col]     = make_float2(c[i][j][0], c[i][j][1]);
            *(float2*)&P[(size_t)(m + g + 8) * D_ + col] = make_float2(c[i][j][2], c[i][j][3]);
        }
    }
}

// ---------------- kernel 2: reduce partials + per-b dot products ----------------
__global__ __launch_bounds__(256) void finalize_a() {
    const int wid = threadIdx.x >> 5, lane = threadIdx.x & 31;
    const int b = blockIdx.x * 8 + wid;
    const int d = lane * 4;

    float4 e = make_float4(0.f, 0.f, 0.f, 0.f);
    float4 p = make_float4(0.f, 0.f, 0.f, 0.f);
    float4 nk[KNEG];
    #pragma unroll
    for (int k = 0; k < KNEG; k++) nk[k] = make_float4(0.f, 0.f, 0.f, 0.f);

    #pragma unroll
    for (int sp = 0; sp < SPLITS; sp++) {
        float4 v;
        v = *(const float4*)&g_part[sp][b][d];
        e.x += v.x; e.y += v.y; e.z += v.z; e.w += v.w;
        v = *(const float4*)&g_part[sp][1024 + b][d];
        p.x += v.x; p.y += v.y; p.z += v.z; p.w += v.w;
        #pragma unroll
        for (int k = 0; k < KNEG; k++) {
            v = *(const float4*)&g_part[sp][2048 + b * KNEG + k][d];
            nk[k].x += v.x; nk[k].y += v.y; nk[k].z += v.z; nk[k].w += v.w;
        }
    }

    float s = e.x * p.x + e.y * p.y + e.z * p.z + e.w * p.w;
    float bm[KNEG];
    #pragma unroll
    for (int k = 0; k < KNEG; k++)
        bm[k] = e.x * nk[k].x + e.y * nk[k].y + e.z * nk[k].z + e.w * nk[k].w;

    #pragma unroll
    for (int off = 16; off; off >>= 1) {
        s += __shfl_xor_sync(0xffffffffu, s, off);
        #pragma unroll
        for (int k = 0; k < KNEG; k++)
            bm[k] += __shfl_xor_sync(0xffffffffu, bm[k], off);
    }
    if (lane == 0) {
        g_s[b] = s;
        #pragma unroll
        for (int k = 0; k < KNEG; k++) g_bm[b * KNEG + k] = bm[k];
    }
}

// ---------------- kernel 3: loss ----------------
__device__ __forceinline__ float logsig(float x) {
    return fminf(x, 0.f) - log1pf(expf(-fabsf(x)));
}

__global__ void finalize_kernel(float* __restrict__ out) {
    __shared__ float red[B_];
    int b = threadIdx.x;
    float left  = logsig(g_s[b]);
    float right = 0.f;
    #pragma unroll
    for (int k = 0; k < KNEG; k++)
        right += logsig(-g_bm[b * KNEG + k]);
    red[b] = -(left + right);
    __syncthreads();
    for (int off = B_ / 2; off > 0; off >>= 1) {
        if (b < off) red[b] += red[b + off];
        __syncthreads();
    }
    if (b == 0) out[0] = red[0] / (float)B_;
}

// ---------------- launch ----------------
extern "C" void kernel_launch(void* const* d_in, const int* in_sizes, int n_in,
                              void* d_out, int out_size) {
    const float* vi  = (const float*)d_in[0];   // [B, VOC]
    const float* vo  = (const float*)d_in[1];   // [B, VOC]
    const float* neg = (const float*)d_in[2];   // [B, K, VOC]
    const float* V   = (const float*)d_in[3];   // [VOC, D]
    const float* U   = (const float*)d_in[4];   // [VOC, D]
    float* out = (float*)d_out;

    gemm_all<<<dim3(RTILES, SPLITS), 256>>>(vi, vo, neg, V, U);
    finalize_a<<<B_ / 8, 256>>>();
    finalize_kernel<<<1, B_>>>(out);
}

// round 16
// speedup vs baseline: 1.2269x; 1.0093x over previous
#include <cuda_runtime.h>
#include <cuda_bf16.h>
#include <math.h>
#include <stdint.h>

#define B_     1024
#define VOCAB  32000
#define D_     128
#define KNEG   5
#define ROWS_T 7168          // 1024 vi + 1024 vo + 5120 neg
#define RTILES 28            // 256-row tiles
#define SPLITS 5
#define CHUNK  6400          // VOCAB / SPLITS
#define ITERS  200           // CHUNK / 32

// smem:  A: [m=256][k=32] bf16, row pitch 80B.  B: [k=32][d=128] bf16,
// row 256B, 16B-chunk XOR-swizzled by (k&7).  Double buffered, 1 CTA/SM.
#define A_ROWB  80
#define A_BUF   (256 * A_ROWB)    // 20480
#define B_BUF   (32 * 256)        // 8192
#define SMEMSZ  (2 * A_BUF + 2 * B_BUF)   // 57344

// ---------------- device scratch ----------------
__device__ float g_part[SPLITS][ROWS_T][D_];   // split-K partials (18.3 MB)

// ---------------- helpers ----------------
__device__ __forceinline__ uint32_t smem_u32(const void* p) {
    uint32_t a;
    asm("{ .reg .u64 t; cvta.to.shared.u64 t, %1; cvt.u32.u64 %0, t; }" : "=r"(a) : "l"(p));
    return a;
}
__device__ __forceinline__ uint32_t pack_bf16(float lo, float hi) {
    uint32_t u;
    asm("cvt.rn.bf16x2.f32 %0, %1, %2;" : "=r"(u) : "f"(hi), "f"(lo));
    return u;
}
__device__ __forceinline__ void ldsm4(uint32_t r[4], uint32_t addr) {
    asm volatile("ldmatrix.sync.aligned.m8n8.x4.shared.b16 {%0,%1,%2,%3}, [%4];"
                 : "=r"(r[0]), "=r"(r[1]), "=r"(r[2]), "=r"(r[3]) : "r"(addr));
}
__device__ __forceinline__ void ldsm4t(uint32_t r[4], uint32_t addr) {
    asm volatile("ldmatrix.sync.aligned.m8n8.x4.trans.shared.b16 {%0,%1,%2,%3}, [%4];"
                 : "=r"(r[0]), "=r"(r[1]), "=r"(r[2]), "=r"(r[3]) : "r"(addr));
}
__device__ __forceinline__ void mma16(float c[4], const uint32_t a[4], const uint32_t b[2]) {
    asm volatile(
        "mma.sync.aligned.m16n8k16.row.col.f32.bf16.bf16.f32 "
        "{%0,%1,%2,%3}, {%4,%5,%6,%7}, {%8,%9}, {%0,%1,%2,%3};"
        : "+f"(c[0]), "+f"(c[1]), "+f"(c[2]), "+f"(c[3])
        : "r"(a[0]), "r"(a[1]), "r"(a[2]), "r"(a[3]), "r"(b[0]), "r"(b[1]));
}

// ---------------- kernel 0: zero the output scalar (poisoned by harness) ----------------
__global__ void zero_out(float* __restrict__ out) {
    out[0] = 0.f;
}

// ---------------- kernel 1: C_part[sp] = X_tile @ Y_chunk  (exact R11 body) ----------------
// CTA tile 256m x 128n, BK=32.  8 warps as 4(m) x 2(n), warp tile 64x64.
// Single __syncthreads per iter: MMA(cur) || STS(it+1) || LDG(it+2).
__global__ __launch_bounds__(256, 1) void gemm_all(const float* __restrict__ vi,
                                                   const float* __restrict__ vo,
                                                   const float* __restrict__ neg,
                                                   const float* __restrict__ V,
                                                   const float* __restrict__ U) {
    __shared__ __align__(16) char smem[SMEMSZ];

    const int mt = blockIdx.x;                // row-tile 0..27
    const int sp = blockIdx.y;                // split   0..4
    const int row0 = mt * 256;
    const float* X = (mt < 4) ? vi  + (size_t)row0 * VOCAB
                   : (mt < 8) ? vo  + (size_t)(row0 - 1024) * VOCAB
                              : neg + (size_t)(row0 - 2048) * VOCAB;
    const float* Y = (mt < 4) ? V : U;
    const int kk0 = sp * CHUNK;

    const int tid = threadIdx.x, lane = tid & 31, wid = tid >> 5;
    const int wm = wid >> 1, wn = wid & 1;    // 4 x 2

    const uint32_t sb = smem_u32(smem);

    // ---- loader roles (coalesced; validated) ----
    const int ar = tid >> 3;                  // A: row within pass (s*32 + ar)
    const int ac = tid & 7;                   // A: float4 col
    const int br = tid >> 5;                  // B: row within pass (s*8 + br)
    const int bc = lane;                      // B: float4 col

    // ---- fragment addresses (validated maps; warp m-span 64) ----
    const uint32_t a_off = (uint32_t)(wm * 64 + (lane & 15)) * A_ROWB + ((lane >> 4) << 4);
    const int kl = (lane & 7) + ((lane >> 3) & 1) * 8;
    uint32_t b_swz[4];
    #pragma unroll
    for (int jj = 0; jj < 4; jj++)
        b_swz[jj] = (uint32_t)(((wn * 8 + jj * 2 + (lane >> 4)) ^ (lane & 7)) << 4);
    const uint32_t b_off = (uint32_t)kl * 256;

    float c[4][8][4] = {};
    float4 xa[8], yb[4];

    // ---- staging helpers ----
    auto do_ldg = [&](int it) {
        const int kk = kk0 + it * 32;
        #pragma unroll
        for (int s = 0; s < 8; s++)
            xa[s] = *(const float4*)(X + (size_t)(s * 32 + ar) * VOCAB + kk + ac * 4);
        #pragma unroll
        for (int s = 0; s < 4; s++)
            yb[s] = *(const float4*)(Y + (size_t)(kk + s * 8 + br) * D_ + bc * 4);
    };
    auto do_sts = [&](uint32_t aoff_buf, uint32_t boff_buf) {
        char* abase = smem + aoff_buf;
        #pragma unroll
        for (int s = 0; s < 8; s++) {
            uint2 v = make_uint2(pack_bf16(xa[s].x, xa[s].y),
                                 pack_bf16(xa[s].z, xa[s].w));
            *(uint2*)(abase + (s * 32 + ar) * A_ROWB + ac * 8) = v;
        }
        char* bbase = smem + 2 * A_BUF + boff_buf;
        #pragma unroll
        for (int s = 0; s < 4; s++) {
            int row = s * 8 + br;
            int chs = (bc >> 1) ^ (row & 7);
            uint2 v = make_uint2(pack_bf16(yb[s].x, yb[s].y),
                                 pack_bf16(yb[s].z, yb[s].w));
            *(uint2*)(bbase + row * 256 + chs * 16 + (bc & 1) * 8) = v;
        }
    };

    // ---- prologue: fill buf0 with iter0, prefetch iter1 into regs ----
    do_ldg(0);
    do_sts(0, 0);
    do_ldg(1);
    __syncthreads();

    for (int it = 0; it < ITERS; it++) {
        const uint32_t cur = (uint32_t)(it & 1);
        const uint32_t abuf = sb + cur * A_BUF;
        const uint32_t bbuf = sb + 2 * A_BUF + cur * B_BUF;

        // ---- MMA on current buffer ----
        #pragma unroll
        for (int ks = 0; ks < 2; ks++) {
            uint32_t af[4][4];
            #pragma unroll
            for (int i = 0; i < 4; i++)
                ldsm4(af[i], abuf + a_off + i * (16 * A_ROWB) + ks * 32);
            const uint32_t brow_b = bbuf + b_off + ks * 16 * 256;
            #pragma unroll
            for (int jj = 0; jj < 4; jj++) {
                uint32_t bf[4];
                ldsm4t(bf, brow_b + b_swz[jj]);
                #pragma unroll
                for (int i = 0; i < 4; i++) {
                    mma16(c[i][jj * 2],     af[i], bf);
                    mma16(c[i][jj * 2 + 1], af[i], bf + 2);
                }
            }
        }

        // ---- stage it+1 into other buffer (disjoint from MMA reads) ----
        if (it + 1 < ITERS)
            do_sts((cur ^ 1) * A_BUF, (cur ^ 1) * B_BUF);
        // ---- prefetch it+2 (regs freed by the STS above) ----
        if (it + 2 < ITERS)
            do_ldg(it + 2);

        __syncthreads();
    }

    // ---- epilogue: disjoint partial writes ----
    const int g = lane >> 2, t = lane & 3;
    float* P = &g_part[sp][row0][0];
    #pragma unroll
    for (int i = 0; i < 4; i++) {
        #pragma unroll
        for (int j = 0; j < 8; j++) {
            int m = wm * 64 + i * 16;
            int col = wn * 64 + j * 8 + 2 * t;
            *(float2*)&P[(size_t)(m + g) * D_ + col]     = make_float2(c[i][j][0], c[i][j][1]);
            *(float2*)&P[(size_t)(m + g + 8) * D_ + col] = make_float2(c[i][j][2], c[i][j][3]);
        }
    }
}

// ---------------- kernel 2: fused reduce + dots + loss ----------------
// one warp per batch row b; lane-0 atomicAdds the per-b loss term into out[0].
__device__ __forceinline__ float logsig(float x) {
    return fminf(x, 0.f) - log1pf(expf(-fabsf(x)));
}

__global__ __launch_bounds__(256) void finalize_fused(float* __restrict__ out) {
    const int wid = threadIdx.x >> 5, lane = threadIdx.x & 31;
    const int b = blockIdx.x * 8 + wid;
    const int d = lane * 4;

    float4 e = make_float4(0.f, 0.f, 0.f, 0.f);
    float4 p = make_float4(0.f, 0.f, 0.f, 0.f);
    float4 nk[KNEG];
    #pragma unroll
    for (int k = 0; k < KNEG; k++) nk[k] = make_float4(0.f, 0.f, 0.f, 0.f);

    #pragma unroll
    for (int sp = 0; sp < SPLITS; sp++) {
        float4 v;
        v = *(const float4*)&g_part[sp][b][d];
        e.x += v.x; e.y += v.y; e.z += v.z; e.w += v.w;
        v = *(const float4*)&g_part[sp][1024 + b][d];
        p.x += v.x; p.y += v.y; p.z += v.z; p.w += v.w;
        #pragma unroll
        for (int k = 0; k < KNEG; k++) {
            v = *(const float4*)&g_part[sp][2048 + b * KNEG + k][d];
            nk[k].x += v.x; nk[k].y += v.y; nk[k].z += v.z; nk[k].w += v.w;
        }
    }

    float s = e.x * p.x + e.y * p.y + e.z * p.z + e.w * p.w;
    float bm[KNEG];
    #pragma unroll
    for (int k = 0; k < KNEG; k++)
        bm[k] = e.x * nk[k].x + e.y * nk[k].y + e.z * nk[k].z + e.w * nk[k].w;

    #pragma unroll
    for (int off = 16; off; off >>= 1) {
        s += __shfl_xor_sync(0xffffffffu, s, off);
        #pragma unroll
        for (int k = 0; k < KNEG; k++)
            bm[k] += __shfl_xor_sync(0xffffffffu, bm[k], off);
    }
    if (lane == 0) {
        float right = 0.f;
        #pragma unroll
        for (int k = 0; k < KNEG; k++)
            right += logsig(-bm[k]);
        float term = -(logsig(s) + right) * (1.0f / (float)B_);
        atomicAdd(out, term);
    }
}

// ---------------- launch ----------------
extern "C" void kernel_launch(void* const* d_in, const int* in_sizes, int n_in,
                              void* d_out, int out_size) {
    const float* vi  = (const float*)d_in[0];   // [B, VOC]
    const float* vo  = (const float*)d_in[1];   // [B, VOC]
    const float* neg = (const float*)d_in[2];   // [B, K, VOC]
    const float* V   = (const float*)d_in[3];   // [VOC, D]
    const float* U   = (const float*)d_in[4];   // [VOC, D]
    float* out = (float*)d_out;

    zero_out<<<1, 1>>>(out);
    gemm_all<<<dim3(RTILES, SPLITS), 256>>>(vi, vo, neg, V, U);
    finalize_fused<<<B_ / 8, 256>>>(out);
}

// round 17
// speedup vs baseline: 1.2365x; 1.0079x over previous
#include <cuda_runtime.h>
#include <cuda_bf16.h>
#include <math.h>
#include <stdint.h>

#define B_     1024
#define VOCAB  32000
#define D_     128
#define KNEG   5
#define ROWS_T 7168          // 1024 vi + 1024 vo + 5120 neg
#define RTILES 28            // 256-row tiles
#define SPLITS 5
#define CHUNK  6400          // VOCAB / SPLITS
#define ITERS  200           // CHUNK / 32

// smem:  A: [m=256][k=32] bf16, row pitch 80B.  B: [k=32][d=128] bf16,
// row 256B, 16B-chunk XOR-swizzled by (k&7).  Double buffered, 1 CTA/SM.
#define A_ROWB  80
#define A_BUF   (256 * A_ROWB)    // 20480
#define B_BUF   (32 * 256)        // 8192
#define SMEMSZ  (2 * A_BUF + 2 * B_BUF)   // 57344

// ---------------- device scratch ----------------
__device__ float g_part[SPLITS][ROWS_T][D_];   // split-K partials (18.3 MB)

// ---------------- helpers ----------------
__device__ __forceinline__ uint32_t smem_u32(const void* p) {
    uint32_t a;
    asm("{ .reg .u64 t; cvta.to.shared.u64 t, %1; cvt.u32.u64 %0, t; }" : "=r"(a) : "l"(p));
    return a;
}
__device__ __forceinline__ uint32_t pack_bf16(float lo, float hi) {
    uint32_t u;
    asm("cvt.rn.bf16x2.f32 %0, %1, %2;" : "=r"(u) : "f"(hi), "f"(lo));
    return u;
}
__device__ __forceinline__ void ldsm4(uint32_t r[4], uint32_t addr) {
    asm volatile("ldmatrix.sync.aligned.m8n8.x4.shared.b16 {%0,%1,%2,%3}, [%4];"
                 : "=r"(r[0]), "=r"(r[1]), "=r"(r[2]), "=r"(r[3]) : "r"(addr));
}
__device__ __forceinline__ void ldsm4t(uint32_t r[4], uint32_t addr) {
    asm volatile("ldmatrix.sync.aligned.m8n8.x4.trans.shared.b16 {%0,%1,%2,%3}, [%4];"
                 : "=r"(r[0]), "=r"(r[1]), "=r"(r[2]), "=r"(r[3]) : "r"(addr));
}
__device__ __forceinline__ void mma16(float c[4], const uint32_t a[4], const uint32_t b[2]) {
    asm volatile(
        "mma.sync.aligned.m16n8k16.row.col.f32.bf16.bf16.f32 "
        "{%0,%1,%2,%3}, {%4,%5,%6,%7}, {%8,%9}, {%0,%1,%2,%3};"
        : "+f"(c[0]), "+f"(c[1]), "+f"(c[2]), "+f"(c[3])
        : "r"(a[0]), "r"(a[1]), "r"(a[2]), "r"(a[3]), "r"(b[0]), "r"(b[1]));
}

// ---------------- kernel 1: C_part[sp] = X_tile @ Y_chunk  (R11 body) ----------------
// CTA tile 256m x 128n, BK=32.  8 warps as 4(m) x 2(n), warp tile 64x64.
// Single __syncthreads per iter: MMA(cur) || STS(it+1) || LDG(it+2).
// Block (0,0) thread 0 also zeroes out[0] (consumed only by the NEXT kernel).
__global__ __launch_bounds__(256, 1) void gemm_all(const float* __restrict__ vi,
                                                   const float* __restrict__ vo,
                                                   const float* __restrict__ neg,
                                                   const float* __restrict__ V,
                                                   const float* __restrict__ U,
                                                   float* __restrict__ out) {
    __shared__ __align__(16) char smem[SMEMSZ];

    const int mt = blockIdx.x;                // row-tile 0..27
    const int sp = blockIdx.y;                // split   0..4

    if (mt == 0 && sp == 0 && threadIdx.x == 0)
        out[0] = 0.f;                         // safe: consumed only after this kernel

    const int row0 = mt * 256;
    const float* X = (mt < 4) ? vi  + (size_t)row0 * VOCAB
                   : (mt < 8) ? vo  + (size_t)(row0 - 1024) * VOCAB
                              : neg + (size_t)(row0 - 2048) * VOCAB;
    const float* Y = (mt < 4) ? V : U;
    const int kk0 = sp * CHUNK;

    const int tid = threadIdx.x, lane = tid & 31, wid = tid >> 5;
    const int wm = wid >> 1, wn = wid & 1;    // 4 x 2

    const uint32_t sb = smem_u32(smem);

    // ---- loader roles (coalesced; validated) ----
    const int ar = tid >> 3;                  // A: row within pass (s*32 + ar)
    const int ac = tid & 7;                   // A: float4 col
    const int br = tid >> 5;                  // B: row within pass (s*8 + br)
    const int bc = lane;                      // B: float4 col

    // ---- fragment addresses (validated maps; warp m-span 64) ----
    const uint32_t a_off = (uint32_t)(wm * 64 + (lane & 15)) * A_ROWB + ((lane >> 4) << 4);
    const int kl = (lane & 7) + ((lane >> 3) & 1) * 8;
    uint32_t b_swz[4];
    #pragma unroll
    for (int jj = 0; jj < 4; jj++)
        b_swz[jj] = (uint32_t)(((wn * 8 + jj * 2 + (lane >> 4)) ^ (lane & 7)) << 4);
    const uint32_t b_off = (uint32_t)kl * 256;

    float c[4][8][4] = {};
    float4 xa[8], yb[4];

    // ---- staging helpers ----
    auto do_ldg = [&](int it) {
        const int kk = kk0 + it * 32;
        #pragma unroll
        for (int s = 0; s < 8; s++)
            xa[s] = *(const float4*)(X + (size_t)(s * 32 + ar) * VOCAB + kk + ac * 4);
        #pragma unroll
        for (int s = 0; s < 4; s++)
            yb[s] = *(const float4*)(Y + (size_t)(kk + s * 8 + br) * D_ + bc * 4);
    };
    auto do_sts = [&](uint32_t aoff_buf, uint32_t boff_buf) {
        char* abase = smem + aoff_buf;
        #pragma unroll
        for (int s = 0; s < 8; s++) {
            uint2 v = make_uint2(pack_bf16(xa[s].x, xa[s].y),
                                 pack_bf16(xa[s].z, xa[s].w));
            *(uint2*)(abase + (s * 32 + ar) * A_ROWB + ac * 8) = v;
        }
        char* bbase = smem + 2 * A_BUF + boff_buf;
        #pragma unroll
        for (int s = 0; s < 4; s++) {
            int row = s * 8 + br;
            int chs = (bc >> 1) ^ (row & 7);
            uint2 v = make_uint2(pack_bf16(yb[s].x, yb[s].y),
                                 pack_bf16(yb[s].z, yb[s].w));
            *(uint2*)(bbase + row * 256 + chs * 16 + (bc & 1) * 8) = v;
        }
    };

    // ---- prologue: fill buf0 with iter0, prefetch iter1 into regs ----
    do_ldg(0);
    do_sts(0, 0);
    do_ldg(1);
    __syncthreads();

    for (int it = 0; it < ITERS; it++) {
        const uint32_t cur = (uint32_t)(it & 1);
        const uint32_t abuf = sb + cur * A_BUF;
        const uint32_t bbuf = sb + 2 * A_BUF + cur * B_BUF;

        // ---- MMA on current buffer ----
        #pragma unroll
        for (int ks = 0; ks < 2; ks++) {
            uint32_t af[4][4];
            #pragma unroll
            for (int i = 0; i < 4; i++)
                ldsm4(af[i], abuf + a_off + i * (16 * A_ROWB) + ks * 32);
            const uint32_t brow_b = bbuf + b_off + ks * 16 * 256;
            #pragma unroll
            for (int jj = 0; jj < 4; jj++) {
                uint32_t bf[4];
                ldsm4t(bf, brow_b + b_swz[jj]);
                #pragma unroll
                for (int i = 0; i < 4; i++) {
                    mma16(c[i][jj * 2],     af[i], bf);
                    mma16(c[i][jj * 2 + 1], af[i], bf + 2);
                }
            }
        }

        // ---- stage it+1 into other buffer (disjoint from MMA reads) ----
        if (it + 1 < ITERS)
            do_sts((cur ^ 1) * A_BUF, (cur ^ 1) * B_BUF);
        // ---- prefetch it+2 (regs freed by the STS above) ----
        if (it + 2 < ITERS)
            do_ldg(it + 2);

        __syncthreads();
    }

    // ---- epilogue: disjoint partial writes ----
    const int g = lane >> 2, t = lane & 3;
    float* P = &g_part[sp][row0][0];
    #pragma unroll
    for (int i = 0; i < 4; i++) {
        #pragma unroll
        for (int j = 0; j < 8; j++) {
            int m = wm * 64 + i * 16;
            int col = wn * 64 + j * 8 + 2 * t;
            *(float2*)&P[(size_t)(m + g) * D_ + col]     = make_float2(c[i][j][0], c[i][j][1]);
            *(float2*)&P[(size_t)(m + g + 8) * D_ + col] = make_float2(c[i][j][2], c[i][j][3]);
        }
    }
}

// ---------------- kernel 2: fused reduce + dots + loss ----------------
// one warp per batch row b; lane-0 atomicAdds the per-b loss term into out[0].
__device__ __forceinline__ float logsig(float x) {
    return fminf(x, 0.f) - log1pf(expf(-fabsf(x)));
}

__global__ __launch_bounds__(256) void finalize_fused(float* __restrict__ out) {
    const int wid = threadIdx.x >> 5, lane = threadIdx.x & 31;
    const int b = blockIdx.x * 8 + wid;
    const int d = lane * 4;

    float4 e = make_float4(0.f, 0.f, 0.f, 0.f);
    float4 p = make_float4(0.f, 0.f, 0.f, 0.f);
    float4 nk[KNEG];
    #pragma unroll
    for (int k = 0; k < KNEG; k++) nk[k] = make_float4(0.f, 0.f, 0.f, 0.f);

    #pragma unroll
    for (int sp = 0; sp < SPLITS; sp++) {
        float4 v;
        v = *(const float4*)&g_part[sp][b][d];
        e.x += v.x; e.y += v.y; e.z += v.z; e.w += v.w;
        v = *(const float4*)&g_part[sp][1024 + b][d];
        p.x += v.x; p.y += v.y; p.z += v.z; p.w += v.w;
        #pragma unroll
        for (int k = 0; k < KNEG; k++) {
            v = *(const float4*)&g_part[sp][2048 + b * KNEG + k][d];
            nk[k].x += v.x; nk[k].y += v.y; nk[k].z += v.z; nk[k].w += v.w;
        }
    }

    float s = e.x * p.x + e.y * p.y + e.z * p.z + e.w * p.w;
    float bm[KNEG];
    #pragma unroll
    for (int k = 0; k < KNEG; k++)
        bm[k] = e.x * nk[k].x + e.y * nk[k].y + e.z * nk[k].z + e.w * nk[k].w;

    #pragma unroll
    for (int off = 16; off; off >>= 1) {
        s += __shfl_xor_sync(0xffffffffu, s, off);
        #pragma unroll
        for (int k = 0; k < KNEG; k++)
            bm[k] += __shfl_xor_sync(0xffffffffu, bm[k], off);
    }
    if (lane == 0) {
        float right = 0.f;
        #pragma unroll
        for (int k = 0; k < KNEG; k++)
            right += logsig(-bm[k]);
        float term = -(logsig(s) + right) * (1.0f / (float)B_);
        atomicAdd(out, term);
    }
}

// ---------------- launch ----------------
extern "C" void kernel_launch(void* const* d_in, const int* in_sizes, int n_in,
                              void* d_out, int out_size) {
    const float* vi  = (const float*)d_in[0];   // [B, VOC]
    const float* vo  = (const float*)d_in[1];   // [B, VOC]
    const float* neg = (const float*)d_in[2];   // [B, K, VOC]
    const float* V   = (const float*)d_in[3];   // [VOC, D]
    const float* U   = (const float*)d_in[4];   // [VOC, D]
    float* out = (float*)d_out;

    gemm_all<<<dim3(RTILES, SPLITS), 256>>>(vi, vo, neg, V, U, out);
    finalize_fused<<<B_ / 8, 256>>>(out);
}